// round 9
// baseline (speedup 1.0000x reference)
#include <cuda_runtime.h>
#include <cuda_bf16.h>

// InterHT triple scoring — single-pass algebraic expansion.
//
// score = -|| hm_n*(T_n+1) + r - tm_n*(H_n+1) ||_2, where _n = L2-normalized.
// Expand ||a + r - b||^2 = Sa + Sb + Sr + 2(a.r) - 2(a.b) - 2(b.r); every term
// decomposes into raw elementwise sums over (h, H, t, T, r) that need no
// normalization before accumulation -> one streaming pass, one reduction.
//
// Inputs (metadata order):
//   d_in[0]: head_emb            float32  (B, 1024)  [0:512)=h(main) [512:1024)=H(aux)
//   d_in[1]: tail_emb            float32  (B, 1024)  [0:512)=t(main) [512:1024)=T(aux)
//   d_in[2]: relation_embedding  float32  (1000, 512)   (2MB -> L2 resident)
//   d_in[3]: relation_id         int32    (B,)
// Output: float32 (B,)

#define EMB 512
#define WARPS_PER_BLOCK 8
#define THREADS (WARPS_PER_BLOCK * 32)
#define EPS 1e-12f

__device__ __forceinline__ float warp_sum(float v) {
    #pragma unroll
    for (int m = 16; m > 0; m >>= 1)
        v += __shfl_xor_sync(0xFFFFFFFFu, v, m);
    return v;
}

// 17 running sums per row (names: h=head_main, H=head_aux, t=tail_main, T=tail_aux, r=rel)
struct Acc {
    float S1, S2, S3, S4;        // Σh², ΣH², Σt², ΣT²
    float A1, A2;                // Σh²T², Σh²T
    float B1, B2;                // Σt²H², Σt²H
    float R0;                    // Σr²
    float C1, C2;                // ΣhTr, Σhr
    float D1, D2;                // ΣtHr, Σtr
    float E1, E2, E3, E4;        // ΣhtTH, ΣhtT, ΣhtH, Σht
};

__device__ __forceinline__ void accum(Acc& a, float h, float H, float t, float T, float r) {
    a.S1 = fmaf(h, h, a.S1);
    a.S2 = fmaf(H, H, a.S2);
    a.S3 = fmaf(t, t, a.S3);
    a.S4 = fmaf(T, T, a.S4);
    const float hT = h * T;
    a.A1 = fmaf(hT, hT, a.A1);
    a.A2 = fmaf(hT, h,  a.A2);
    const float tH = t * H;
    a.B1 = fmaf(tH, tH, a.B1);
    a.B2 = fmaf(tH, t,  a.B2);
    a.R0 = fmaf(r, r, a.R0);
    a.C1 = fmaf(hT, r, a.C1);
    a.C2 = fmaf(h,  r, a.C2);
    a.D1 = fmaf(tH, r, a.D1);
    a.D2 = fmaf(t,  r, a.D2);
    const float ht = h * t;
    a.E1 = fmaf(hT, tH, a.E1);
    a.E2 = fmaf(ht, T,  a.E2);
    a.E3 = fmaf(ht, H,  a.E3);
    a.E4 += ht;
}

__global__ void __launch_bounds__(THREADS, 3)
interht_kernel(const float* __restrict__ head,
               const float* __restrict__ tail,
               const float* __restrict__ rel_tab,
               const int*   __restrict__ rel_id,
               float* __restrict__ out,
               int B)
{
    const int warp_in_blk = threadIdx.x >> 5;
    const int lane        = threadIdx.x & 31;
    const int row         = blockIdx.x * WARPS_PER_BLOCK + warp_in_blk;
    if (row >= B) return;

    const int rid = __ldg(&rel_id[row]);

    const float4* h_p = reinterpret_cast<const float4*>(head + (size_t)row * 1024);
    const float4* H_p = h_p + (EMB / 4);
    const float4* t_p = reinterpret_cast<const float4*>(tail + (size_t)row * 1024);
    const float4* T_p = t_p + (EMB / 4);
    const float4* r_p = reinterpret_cast<const float4*>(rel_tab + (size_t)rid * EMB);

    Acc a = {};

    #pragma unroll
    for (int c = 0; c < 4; c++) {
        const int idx = c * 32 + lane;
        const float4 h4 = h_p[idx];
        const float4 H4 = H_p[idx];
        const float4 t4 = t_p[idx];
        const float4 T4 = T_p[idx];
        const float4 r4 = r_p[idx];
        accum(a, h4.x, H4.x, t4.x, T4.x, r4.x);
        accum(a, h4.y, H4.y, t4.y, T4.y, r4.y);
        accum(a, h4.z, H4.z, t4.z, T4.z, r4.z);
        accum(a, h4.w, H4.w, t4.w, T4.w, r4.w);
    }

    // One reduction round: 17 independent butterfly sums.
    a.S1 = warp_sum(a.S1);  a.S2 = warp_sum(a.S2);
    a.S3 = warp_sum(a.S3);  a.S4 = warp_sum(a.S4);
    a.A1 = warp_sum(a.A1);  a.A2 = warp_sum(a.A2);
    a.B1 = warp_sum(a.B1);  a.B2 = warp_sum(a.B2);
    a.R0 = warp_sum(a.R0);
    a.C1 = warp_sum(a.C1);  a.C2 = warp_sum(a.C2);
    a.D1 = warp_sum(a.D1);  a.D2 = warp_sum(a.D2);
    a.E1 = warp_sum(a.E1);  a.E2 = warp_sum(a.E2);
    a.E3 = warp_sum(a.E3);  a.E4 = warp_sum(a.E4);

    if (lane == 0) {
        const float inh = 1.0f / fmaxf(sqrtf(a.S1), EPS);
        const float inH = 1.0f / fmaxf(sqrtf(a.S2), EPS);
        const float int_ = 1.0f / fmaxf(sqrtf(a.S3), EPS);
        const float inT = 1.0f / fmaxf(sqrtf(a.S4), EPS);

        // ||a||^2 = (A1*inT^2 + 2*A2*inT + S1) * inh^2
        const float Sa  = (a.A1 * inT * inT + 2.0f * a.A2 * inT + a.S1) * (inh * inh);
        // ||b||^2 = (B1*inH^2 + 2*B2*inH + S3) * int^2
        const float Sb  = (a.B1 * inH * inH + 2.0f * a.B2 * inH + a.S3) * (int_ * int_);
        // a.r = (C1*inT + C2)*inh ;  b.r = (D1*inH + D2)*int
        const float Sar = (a.C1 * inT + a.C2) * inh;
        const float Sbr = (a.D1 * inH + a.D2) * int_;
        // a.b = (E1*inT*inH + E2*inT + E3*inH + E4) * inh*int
        const float Sab = ((a.E1 * inH + a.E2) * inT + a.E3 * inH + a.E4) * (inh * int_);

        const float dd = Sa + Sb + a.R0 + 2.0f * (Sar - Sbr - Sab);
        out[row] = -sqrtf(fmaxf(dd, 0.0f));
    }
}

extern "C" void kernel_launch(void* const* d_in, const int* in_sizes, int n_in,
                              void* d_out, int out_size)
{
    const float* head    = (const float*)d_in[0];
    const float* tail    = (const float*)d_in[1];
    const float* rel_tab = (const float*)d_in[2];
    const int*   rel_id  = (const int*)d_in[3];
    float*       out     = (float*)d_out;

    const int B = in_sizes[0] / 1024;  // head_emb is (B, 2*512)
    const int blocks = (B + WARPS_PER_BLOCK - 1) / WARPS_PER_BLOCK;
    interht_kernel<<<blocks, THREADS>>>(head, tail, rel_tab, rel_id, out, B);
}

// round 10
// speedup vs baseline: 1.0051x; 1.0051x over previous
#include <cuda_runtime.h>
#include <cuda_bf16.h>

// InterHT triple scoring — single-pass algebraic expansion.
//
// score = -|| hm_n*(T_n+1) + r - tm_n*(H_n+1) ||_2, where _n = L2-normalized.
// Expand ||a + r - b||^2 = Sa + Sb + Sr + 2(a.r) - 2(a.b) - 2(b.r); every term
// decomposes into raw elementwise sums over (h, H, t, T, r) that need no
// normalization before accumulation -> one streaming pass, one reduction.
//
// Inputs (metadata order):
//   d_in[0]: head_emb            float32  (B, 1024)  [0:512)=h(main) [512:1024)=H(aux)
//   d_in[1]: tail_emb            float32  (B, 1024)  [0:512)=t(main) [512:1024)=T(aux)
//   d_in[2]: relation_embedding  float32  (1000, 512)   (2MB -> L2 resident)
//   d_in[3]: relation_id         int32    (B,)
// Output: float32 (B,)

#define EMB 512
#define WARPS_PER_BLOCK 8
#define THREADS (WARPS_PER_BLOCK * 32)
#define EPS 1e-12f

__device__ __forceinline__ float warp_sum(float v) {
    #pragma unroll
    for (int m = 16; m > 0; m >>= 1)
        v += __shfl_xor_sync(0xFFFFFFFFu, v, m);
    return v;
}

// 17 running sums per row (names: h=head_main, H=head_aux, t=tail_main, T=tail_aux, r=rel)
struct Acc {
    float S1, S2, S3, S4;        // Σh², ΣH², Σt², ΣT²
    float A1, A2;                // Σh²T², Σh²T
    float B1, B2;                // Σt²H², Σt²H
    float R0;                    // Σr²
    float C1, C2;                // ΣhTr, Σhr
    float D1, D2;                // ΣtHr, Σtr
    float E1, E2, E3, E4;        // ΣhtTH, ΣhtT, ΣhtH, Σht
};

__device__ __forceinline__ void accum(Acc& a, float h, float H, float t, float T, float r) {
    a.S1 = fmaf(h, h, a.S1);
    a.S2 = fmaf(H, H, a.S2);
    a.S3 = fmaf(t, t, a.S3);
    a.S4 = fmaf(T, T, a.S4);
    const float hT = h * T;
    a.A1 = fmaf(hT, hT, a.A1);
    a.A2 = fmaf(hT, h,  a.A2);
    const float tH = t * H;
    a.B1 = fmaf(tH, tH, a.B1);
    a.B2 = fmaf(tH, t,  a.B2);
    a.R0 = fmaf(r, r, a.R0);
    a.C1 = fmaf(hT, r, a.C1);
    a.C2 = fmaf(h,  r, a.C2);
    a.D1 = fmaf(tH, r, a.D1);
    a.D2 = fmaf(t,  r, a.D2);
    const float ht = h * t;
    a.E1 = fmaf(hT, tH, a.E1);
    a.E2 = fmaf(ht, T,  a.E2);
    a.E3 = fmaf(ht, H,  a.E3);
    a.E4 += ht;
}

__global__ void __launch_bounds__(THREADS, 3)
interht_kernel(const float* __restrict__ head,
               const float* __restrict__ tail,
               const float* __restrict__ rel_tab,
               const int*   __restrict__ rel_id,
               float* __restrict__ out,
               int B)
{
    const int warp_in_blk = threadIdx.x >> 5;
    const int lane        = threadIdx.x & 31;
    const int row         = blockIdx.x * WARPS_PER_BLOCK + warp_in_blk;
    if (row >= B) return;

    const int rid = __ldg(&rel_id[row]);

    const float4* h_p = reinterpret_cast<const float4*>(head + (size_t)row * 1024);
    const float4* H_p = h_p + (EMB / 4);
    const float4* t_p = reinterpret_cast<const float4*>(tail + (size_t)row * 1024);
    const float4* T_p = t_p + (EMB / 4);
    const float4* r_p = reinterpret_cast<const float4*>(rel_tab + (size_t)rid * EMB);

    Acc a = {};

    #pragma unroll
    for (int c = 0; c < 4; c++) {
        const int idx = c * 32 + lane;
        const float4 h4 = h_p[idx];
        const float4 H4 = H_p[idx];
        const float4 t4 = t_p[idx];
        const float4 T4 = T_p[idx];
        const float4 r4 = r_p[idx];
        accum(a, h4.x, H4.x, t4.x, T4.x, r4.x);
        accum(a, h4.y, H4.y, t4.y, T4.y, r4.y);
        accum(a, h4.z, H4.z, t4.z, T4.z, r4.z);
        accum(a, h4.w, H4.w, t4.w, T4.w, r4.w);
    }

    // One reduction round: 17 independent butterfly sums.
    a.S1 = warp_sum(a.S1);  a.S2 = warp_sum(a.S2);
    a.S3 = warp_sum(a.S3);  a.S4 = warp_sum(a.S4);
    a.A1 = warp_sum(a.A1);  a.A2 = warp_sum(a.A2);
    a.B1 = warp_sum(a.B1);  a.B2 = warp_sum(a.B2);
    a.R0 = warp_sum(a.R0);
    a.C1 = warp_sum(a.C1);  a.C2 = warp_sum(a.C2);
    a.D1 = warp_sum(a.D1);  a.D2 = warp_sum(a.D2);
    a.E1 = warp_sum(a.E1);  a.E2 = warp_sum(a.E2);
    a.E3 = warp_sum(a.E3);  a.E4 = warp_sum(a.E4);

    if (lane == 0) {
        const float inh = 1.0f / fmaxf(sqrtf(a.S1), EPS);
        const float inH = 1.0f / fmaxf(sqrtf(a.S2), EPS);
        const float int_ = 1.0f / fmaxf(sqrtf(a.S3), EPS);
        const float inT = 1.0f / fmaxf(sqrtf(a.S4), EPS);

        // ||a||^2 = (A1*inT^2 + 2*A2*inT + S1) * inh^2
        const float Sa  = (a.A1 * inT * inT + 2.0f * a.A2 * inT + a.S1) * (inh * inh);
        // ||b||^2 = (B1*inH^2 + 2*B2*inH + S3) * int^2
        const float Sb  = (a.B1 * inH * inH + 2.0f * a.B2 * inH + a.S3) * (int_ * int_);
        // a.r = (C1*inT + C2)*inh ;  b.r = (D1*inH + D2)*int
        const float Sar = (a.C1 * inT + a.C2) * inh;
        const float Sbr = (a.D1 * inH + a.D2) * int_;
        // a.b = (E1*inT*inH + E2*inT + E3*inH + E4) * inh*int
        const float Sab = ((a.E1 * inH + a.E2) * inT + a.E3 * inH + a.E4) * (inh * int_);

        const float dd = Sa + Sb + a.R0 + 2.0f * (Sar - Sbr - Sab);
        out[row] = -sqrtf(fmaxf(dd, 0.0f));
    }
}

extern "C" void kernel_launch(void* const* d_in, const int* in_sizes, int n_in,
                              void* d_out, int out_size)
{
    const float* head    = (const float*)d_in[0];
    const float* tail    = (const float*)d_in[1];
    const float* rel_tab = (const float*)d_in[2];
    const int*   rel_id  = (const int*)d_in[3];
    float*       out     = (float*)d_out;

    const int B = in_sizes[0] / 1024;  // head_emb is (B, 2*512)
    const int blocks = (B + WARPS_PER_BLOCK - 1) / WARPS_PER_BLOCK;
    interht_kernel<<<blocks, THREADS>>>(head, tail, rel_tab, rel_id, out, B);
}

// round 11
// speedup vs baseline: 1.0095x; 1.0043x over previous
#include <cuda_runtime.h>
#include <cuda_bf16.h>

// InterHT triple scoring — single-pass algebraic expansion.
//
// score = -|| hm_n*(T_n+1) + r - tm_n*(H_n+1) ||_2, where _n = L2-normalized.
// Expand ||a + r - b||^2 = Sa + Sb + Sr + 2(a.r) - 2(a.b) - 2(b.r); every term
// decomposes into raw elementwise sums over (h, H, t, T, r) that need no
// normalization before accumulation -> one streaming pass, one reduction.
//
// Inputs (metadata order):
//   d_in[0]: head_emb            float32  (B, 1024)  [0:512)=h(main) [512:1024)=H(aux)
//   d_in[1]: tail_emb            float32  (B, 1024)  [0:512)=t(main) [512:1024)=T(aux)
//   d_in[2]: relation_embedding  float32  (1000, 512)   (2MB -> L2 resident)
//   d_in[3]: relation_id         int32    (B,)
// Output: float32 (B,)

#define EMB 512
#define WARPS_PER_BLOCK 8
#define THREADS (WARPS_PER_BLOCK * 32)
#define EPS 1e-12f

__device__ __forceinline__ float warp_sum(float v) {
    #pragma unroll
    for (int m = 16; m > 0; m >>= 1)
        v += __shfl_xor_sync(0xFFFFFFFFu, v, m);
    return v;
}

// 17 running sums per row (names: h=head_main, H=head_aux, t=tail_main, T=tail_aux, r=rel)
struct Acc {
    float S1, S2, S3, S4;        // Σh², ΣH², Σt², ΣT²
    float A1, A2;                // Σh²T², Σh²T
    float B1, B2;                // Σt²H², Σt²H
    float R0;                    // Σr²
    float C1, C2;                // ΣhTr, Σhr
    float D1, D2;                // ΣtHr, Σtr
    float E1, E2, E3, E4;        // ΣhtTH, ΣhtT, ΣhtH, Σht
};

__device__ __forceinline__ void accum(Acc& a, float h, float H, float t, float T, float r) {
    a.S1 = fmaf(h, h, a.S1);
    a.S2 = fmaf(H, H, a.S2);
    a.S3 = fmaf(t, t, a.S3);
    a.S4 = fmaf(T, T, a.S4);
    const float hT = h * T;
    a.A1 = fmaf(hT, hT, a.A1);
    a.A2 = fmaf(hT, h,  a.A2);
    const float tH = t * H;
    a.B1 = fmaf(tH, tH, a.B1);
    a.B2 = fmaf(tH, t,  a.B2);
    a.R0 = fmaf(r, r, a.R0);
    a.C1 = fmaf(hT, r, a.C1);
    a.C2 = fmaf(h,  r, a.C2);
    a.D1 = fmaf(tH, r, a.D1);
    a.D2 = fmaf(t,  r, a.D2);
    const float ht = h * t;
    a.E1 = fmaf(hT, tH, a.E1);
    a.E2 = fmaf(ht, T,  a.E2);
    a.E3 = fmaf(ht, H,  a.E3);
    a.E4 += ht;
}

__global__ void __launch_bounds__(THREADS, 3)
interht_kernel(const float* __restrict__ head,
               const float* __restrict__ tail,
               const float* __restrict__ rel_tab,
               const int*   __restrict__ rel_id,
               float* __restrict__ out,
               int B)
{
    const int warp_in_blk = threadIdx.x >> 5;
    const int lane        = threadIdx.x & 31;
    const int row         = blockIdx.x * WARPS_PER_BLOCK + warp_in_blk;
    if (row >= B) return;

    const int rid = __ldg(&rel_id[row]);

    const float4* h_p = reinterpret_cast<const float4*>(head + (size_t)row * 1024);
    const float4* H_p = h_p + (EMB / 4);
    const float4* t_p = reinterpret_cast<const float4*>(tail + (size_t)row * 1024);
    const float4* T_p = t_p + (EMB / 4);
    const float4* r_p = reinterpret_cast<const float4*>(rel_tab + (size_t)rid * EMB);

    Acc a = {};

    #pragma unroll
    for (int c = 0; c < 4; c++) {
        const int idx = c * 32 + lane;
        const float4 h4 = h_p[idx];
        const float4 H4 = H_p[idx];
        const float4 t4 = t_p[idx];
        const float4 T4 = T_p[idx];
        const float4 r4 = r_p[idx];
        accum(a, h4.x, H4.x, t4.x, T4.x, r4.x);
        accum(a, h4.y, H4.y, t4.y, T4.y, r4.y);
        accum(a, h4.z, H4.z, t4.z, T4.z, r4.z);
        accum(a, h4.w, H4.w, t4.w, T4.w, r4.w);
    }

    // One reduction round: 17 independent butterfly sums.
    a.S1 = warp_sum(a.S1);  a.S2 = warp_sum(a.S2);
    a.S3 = warp_sum(a.S3);  a.S4 = warp_sum(a.S4);
    a.A1 = warp_sum(a.A1);  a.A2 = warp_sum(a.A2);
    a.B1 = warp_sum(a.B1);  a.B2 = warp_sum(a.B2);
    a.R0 = warp_sum(a.R0);
    a.C1 = warp_sum(a.C1);  a.C2 = warp_sum(a.C2);
    a.D1 = warp_sum(a.D1);  a.D2 = warp_sum(a.D2);
    a.E1 = warp_sum(a.E1);  a.E2 = warp_sum(a.E2);
    a.E3 = warp_sum(a.E3);  a.E4 = warp_sum(a.E4);

    if (lane == 0) {
        const float inh = 1.0f / fmaxf(sqrtf(a.S1), EPS);
        const float inH = 1.0f / fmaxf(sqrtf(a.S2), EPS);
        const float int_ = 1.0f / fmaxf(sqrtf(a.S3), EPS);
        const float inT = 1.0f / fmaxf(sqrtf(a.S4), EPS);

        // ||a||^2 = (A1*inT^2 + 2*A2*inT + S1) * inh^2
        const float Sa  = (a.A1 * inT * inT + 2.0f * a.A2 * inT + a.S1) * (inh * inh);
        // ||b||^2 = (B1*inH^2 + 2*B2*inH + S3) * int^2
        const float Sb  = (a.B1 * inH * inH + 2.0f * a.B2 * inH + a.S3) * (int_ * int_);
        // a.r = (C1*inT + C2)*inh ;  b.r = (D1*inH + D2)*int
        const float Sar = (a.C1 * inT + a.C2) * inh;
        const float Sbr = (a.D1 * inH + a.D2) * int_;
        // a.b = (E1*inT*inH + E2*inT + E3*inH + E4) * inh*int
        const float Sab = ((a.E1 * inH + a.E2) * inT + a.E3 * inH + a.E4) * (inh * int_);

        const float dd = Sa + Sb + a.R0 + 2.0f * (Sar - Sbr - Sab);
        out[row] = -sqrtf(fmaxf(dd, 0.0f));
    }
}

extern "C" void kernel_launch(void* const* d_in, const int* in_sizes, int n_in,
                              void* d_out, int out_size)
{
    const float* head    = (const float*)d_in[0];
    const float* tail    = (const float*)d_in[1];
    const float* rel_tab = (const float*)d_in[2];
    const int*   rel_id  = (const int*)d_in[3];
    float*       out     = (float*)d_out;

    const int B = in_sizes[0] / 1024;  // head_emb is (B, 2*512)
    const int blocks = (B + WARPS_PER_BLOCK - 1) / WARPS_PER_BLOCK;
    interht_kernel<<<blocks, THREADS>>>(head, tail, rel_tab, rel_id, out, B);
}

// round 12
// speedup vs baseline: 1.0141x; 1.0046x over previous
#include <cuda_runtime.h>
#include <cuda_bf16.h>

// InterHT triple scoring — single-pass algebraic expansion.
//
// score = -|| hm_n*(T_n+1) + r - tm_n*(H_n+1) ||_2, where _n = L2-normalized.
// Expand ||a + r - b||^2 = Sa + Sb + Sr + 2(a.r) - 2(a.b) - 2(b.r); every term
// decomposes into raw elementwise sums over (h, H, t, T, r) that need no
// normalization before accumulation -> one streaming pass, one reduction.
//
// Inputs (metadata order):
//   d_in[0]: head_emb            float32  (B, 1024)  [0:512)=h(main) [512:1024)=H(aux)
//   d_in[1]: tail_emb            float32  (B, 1024)  [0:512)=t(main) [512:1024)=T(aux)
//   d_in[2]: relation_embedding  float32  (1000, 512)   (2MB -> L2 resident)
//   d_in[3]: relation_id         int32    (B,)
// Output: float32 (B,)

#define EMB 512
#define WARPS_PER_BLOCK 8
#define THREADS (WARPS_PER_BLOCK * 32)
#define EPS 1e-12f

__device__ __forceinline__ float warp_sum(float v) {
    #pragma unroll
    for (int m = 16; m > 0; m >>= 1)
        v += __shfl_xor_sync(0xFFFFFFFFu, v, m);
    return v;
}

// 17 running sums per row (names: h=head_main, H=head_aux, t=tail_main, T=tail_aux, r=rel)
struct Acc {
    float S1, S2, S3, S4;        // Σh², ΣH², Σt², ΣT²
    float A1, A2;                // Σh²T², Σh²T
    float B1, B2;                // Σt²H², Σt²H
    float R0;                    // Σr²
    float C1, C2;                // ΣhTr, Σhr
    float D1, D2;                // ΣtHr, Σtr
    float E1, E2, E3, E4;        // ΣhtTH, ΣhtT, ΣhtH, Σht
};

__device__ __forceinline__ void accum(Acc& a, float h, float H, float t, float T, float r) {
    a.S1 = fmaf(h, h, a.S1);
    a.S2 = fmaf(H, H, a.S2);
    a.S3 = fmaf(t, t, a.S3);
    a.S4 = fmaf(T, T, a.S4);
    const float hT = h * T;
    a.A1 = fmaf(hT, hT, a.A1);
    a.A2 = fmaf(hT, h,  a.A2);
    const float tH = t * H;
    a.B1 = fmaf(tH, tH, a.B1);
    a.B2 = fmaf(tH, t,  a.B2);
    a.R0 = fmaf(r, r, a.R0);
    a.C1 = fmaf(hT, r, a.C1);
    a.C2 = fmaf(h,  r, a.C2);
    a.D1 = fmaf(tH, r, a.D1);
    a.D2 = fmaf(t,  r, a.D2);
    const float ht = h * t;
    a.E1 = fmaf(hT, tH, a.E1);
    a.E2 = fmaf(ht, T,  a.E2);
    a.E3 = fmaf(ht, H,  a.E3);
    a.E4 += ht;
}

__global__ void __launch_bounds__(THREADS, 3)
interht_kernel(const float* __restrict__ head,
               const float* __restrict__ tail,
               const float* __restrict__ rel_tab,
               const int*   __restrict__ rel_id,
               float* __restrict__ out,
               int B)
{
    const int warp_in_blk = threadIdx.x >> 5;
    const int lane        = threadIdx.x & 31;
    const int row         = blockIdx.x * WARPS_PER_BLOCK + warp_in_blk;
    if (row >= B) return;

    const int rid = __ldg(&rel_id[row]);

    const float4* h_p = reinterpret_cast<const float4*>(head + (size_t)row * 1024);
    const float4* H_p = h_p + (EMB / 4);
    const float4* t_p = reinterpret_cast<const float4*>(tail + (size_t)row * 1024);
    const float4* T_p = t_p + (EMB / 4);
    const float4* r_p = reinterpret_cast<const float4*>(rel_tab + (size_t)rid * EMB);

    Acc a = {};

    #pragma unroll
    for (int c = 0; c < 4; c++) {
        const int idx = c * 32 + lane;
        const float4 h4 = h_p[idx];
        const float4 H4 = H_p[idx];
        const float4 t4 = t_p[idx];
        const float4 T4 = T_p[idx];
        const float4 r4 = r_p[idx];
        accum(a, h4.x, H4.x, t4.x, T4.x, r4.x);
        accum(a, h4.y, H4.y, t4.y, T4.y, r4.y);
        accum(a, h4.z, H4.z, t4.z, T4.z, r4.z);
        accum(a, h4.w, H4.w, t4.w, T4.w, r4.w);
    }

    // One reduction round: 17 independent butterfly sums.
    a.S1 = warp_sum(a.S1);  a.S2 = warp_sum(a.S2);
    a.S3 = warp_sum(a.S3);  a.S4 = warp_sum(a.S4);
    a.A1 = warp_sum(a.A1);  a.A2 = warp_sum(a.A2);
    a.B1 = warp_sum(a.B1);  a.B2 = warp_sum(a.B2);
    a.R0 = warp_sum(a.R0);
    a.C1 = warp_sum(a.C1);  a.C2 = warp_sum(a.C2);
    a.D1 = warp_sum(a.D1);  a.D2 = warp_sum(a.D2);
    a.E1 = warp_sum(a.E1);  a.E2 = warp_sum(a.E2);
    a.E3 = warp_sum(a.E3);  a.E4 = warp_sum(a.E4);

    if (lane == 0) {
        const float inh = 1.0f / fmaxf(sqrtf(a.S1), EPS);
        const float inH = 1.0f / fmaxf(sqrtf(a.S2), EPS);
        const float int_ = 1.0f / fmaxf(sqrtf(a.S3), EPS);
        const float inT = 1.0f / fmaxf(sqrtf(a.S4), EPS);

        // ||a||^2 = (A1*inT^2 + 2*A2*inT + S1) * inh^2
        const float Sa  = (a.A1 * inT * inT + 2.0f * a.A2 * inT + a.S1) * (inh * inh);
        // ||b||^2 = (B1*inH^2 + 2*B2*inH + S3) * int^2
        const float Sb  = (a.B1 * inH * inH + 2.0f * a.B2 * inH + a.S3) * (int_ * int_);
        // a.r = (C1*inT + C2)*inh ;  b.r = (D1*inH + D2)*int
        const float Sar = (a.C1 * inT + a.C2) * inh;
        const float Sbr = (a.D1 * inH + a.D2) * int_;
        // a.b = (E1*inT*inH + E2*inT + E3*inH + E4) * inh*int
        const float Sab = ((a.E1 * inH + a.E2) * inT + a.E3 * inH + a.E4) * (inh * int_);

        const float dd = Sa + Sb + a.R0 + 2.0f * (Sar - Sbr - Sab);
        out[row] = -sqrtf(fmaxf(dd, 0.0f));
    }
}

extern "C" void kernel_launch(void* const* d_in, const int* in_sizes, int n_in,
                              void* d_out, int out_size)
{
    const float* head    = (const float*)d_in[0];
    const float* tail    = (const float*)d_in[1];
    const float* rel_tab = (const float*)d_in[2];
    const int*   rel_id  = (const int*)d_in[3];
    float*       out     = (float*)d_out;

    const int B = in_sizes[0] / 1024;  // head_emb is (B, 2*512)
    const int blocks = (B + WARPS_PER_BLOCK - 1) / WARPS_PER_BLOCK;
    interht_kernel<<<blocks, THREADS>>>(head, tail, rel_tab, rel_id, out, B);
}